// round 7
// baseline (speedup 1.0000x reference)
#include <cuda_runtime.h>
#include <cuda_fp16.h>
#include <cstdint>

// ============================================================================
// LSTMCell for GB300 — sm_103 (non-'a') path: fp16 mma.sync + cp.async.bulk.
//
//   Pass 1 (single kernel): fp32 -> fp16 (RN), pre-tiled + SW128-swizzled.
//   Pass 2: GEMM 128x128x(BK=64), 3-stage bulk-copy mbarrier ring.
//           Per-ks: hoisted A-block LDSM (4x ldmatrix.x4) + B prefetch (ks+1),
//           seam preload of next stage's B.  Fused fast-math LSTM epilogue.
// ============================================================================

#define DINLINE __device__ __forceinline__

__device__ __align__(1024) __half g_Ah[4096UL * 4096];   // 32 MB
__device__ __align__(1024) __half g_Bh[8192UL * 4096];   // 64 MB

// ------------------------------- helpers -----------------------------------
DINLINE uint32_t smem_u32(const void* p) {
    uint32_t a;
    asm("{ .reg .u64 t; cvta.to.shared.u64 t, %1; cvt.u32.u64 %0, t; }"
        : "=r"(a) : "l"(p));
    return a;
}

DINLINE void mbar_init(uint32_t a, uint32_t cnt) {
    asm volatile("mbarrier.init.shared.b64 [%0], %1;" :: "r"(a), "r"(cnt) : "memory");
}
DINLINE void mbar_expect(uint32_t a, uint32_t tx) {
    asm volatile("mbarrier.arrive.expect_tx.shared.b64 _, [%0], %1;"
                 :: "r"(a), "r"(tx) : "memory");
}
DINLINE void mbar_arrive(uint32_t a) {
    asm volatile("mbarrier.arrive.shared.b64 _, [%0];" :: "r"(a) : "memory");
}
DINLINE void mbar_wait(uint32_t mbar, uint32_t parity) {
    uint32_t done;
    asm volatile(
        "{\n .reg .pred p;\n"
        " mbarrier.try_wait.parity.acquire.cta.shared::cta.b64 p, [%1], %2;\n"
        " selp.b32 %0, 1, 0, p;\n}"
        : "=r"(done) : "r"(mbar), "r"(parity) : "memory");
    if (!done) {
        asm volatile(
            "{\n .reg .pred P1;\n"
            "WL%=:\n"
            " mbarrier.try_wait.parity.acquire.cta.shared::cta.b64 P1, [%0], %1, 0x989680;\n"
            " @P1 bra.uni WD%=;\n"
            " bra.uni WL%=;\n"
            "WD%=:\n}"
            :: "r"(mbar), "r"(parity) : "memory");
    }
}

DINLINE void bulk_g2s(uint32_t dst, const void* src, uint32_t bytes, uint32_t mbar) {
    asm volatile(
        "cp.async.bulk.shared::cluster.global.mbarrier::complete_tx::bytes [%0], [%1], %2, [%3];"
        :: "r"(dst), "l"(src), "r"(bytes), "r"(mbar) : "memory");
}

// fast-math gates (ex2/rcp approx; errors ~1e-7, negligible vs fp16 inputs)
DINLINE float ex2a(float x) { float y; asm("ex2.approx.f32 %0, %1;" : "=f"(y) : "f"(x)); return y; }
DINLINE float rcpa(float x) { float y; asm("rcp.approx.f32 %0, %1;" : "=f"(y) : "f"(x)); return y; }
DINLINE float sigf(float x)  { return rcpa(1.0f + ex2a(-1.442695041f * x)); }
DINLINE float tanhp(float x) { return 2.0f * sigf(2.0f * x) - 1.0f; }

// ============================================================================
// Pass 1: convert + tile + swizzle.  Chunk = 16B of fp16 (8 halves).
// ============================================================================
struct CvtIn { float4 v0, v1; };

DINLINE const float* chunk_src(const float* a, const float* b,
                               uint32_t t, int which)
{
    const uint32_t c = t & 7u;
    const uint32_t m = (t >> 3) & 127u;
    const uint32_t k = ((t >> 10) & 63u) * 64u + c * 8u;
    const uint32_t tile = t >> 16;
    uint32_t src_row;
    if (which) src_row = ((m >> 5) << 11) + tile * 32u + (m & 31u);
    else       src_row = tile * 128u + m;
    const size_t srow = (size_t)src_row * 2048;
    return (k < 2048u) ? (a + srow + k) : (b + srow + (k - 2048u));
}

DINLINE void chunk_store(__half* dstbuf, uint32_t t, const CvtIn& in)
{
    __half2 h0 = __floats2half2_rn(in.v0.x, in.v0.y);
    __half2 h1 = __floats2half2_rn(in.v0.z, in.v0.w);
    __half2 h2 = __floats2half2_rn(in.v1.x, in.v1.y);
    __half2 h3 = __floats2half2_rn(in.v1.z, in.v1.w);
    uint4 out;
    out.x = *reinterpret_cast<uint32_t*>(&h0);
    out.y = *reinterpret_cast<uint32_t*>(&h1);
    out.z = *reinterpret_cast<uint32_t*>(&h2);
    out.w = *reinterpret_cast<uint32_t*>(&h3);
    const uint32_t c = t & 7u, m = (t >> 3) & 127u;
    *reinterpret_cast<uint4*>((unsigned char*)dstbuf +
        ((size_t)(t >> 3) << 7) + ((c ^ (m & 7u)) << 4)) = out;
}

__global__ __launch_bounds__(256)
void cvt_pack(const float* __restrict__ x,  const float* __restrict__ h,
              const float* __restrict__ wi, const float* __restrict__ wh)
{
    const uint32_t g = blockIdx.x * 256u + threadIdx.x;
    if (g < (1u << 20)) {
        const uint32_t t0 = g, t1 = g + (1u << 20);
        const float* s0 = chunk_src(x, h, t0, 0);
        const float* s1 = chunk_src(x, h, t1, 0);
        CvtIn i0, i1;
        i0.v0 = *reinterpret_cast<const float4*>(s0);
        i0.v1 = *reinterpret_cast<const float4*>(s0 + 4);
        i1.v0 = *reinterpret_cast<const float4*>(s1);
        i1.v1 = *reinterpret_cast<const float4*>(s1 + 4);
        chunk_store(g_Ah, t0, i0);
        chunk_store(g_Ah, t1, i1);
    } else {
        const uint32_t q = g - (1u << 20);
        const uint32_t t0 = q, t1 = q + (1u << 21);
        const float* s0 = chunk_src(wi, wh, t0, 1);
        const float* s1 = chunk_src(wi, wh, t1, 1);
        CvtIn i0, i1;
        i0.v0 = *reinterpret_cast<const float4*>(s0);
        i0.v1 = *reinterpret_cast<const float4*>(s0 + 4);
        i1.v0 = *reinterpret_cast<const float4*>(s1);
        i1.v1 = *reinterpret_cast<const float4*>(s1 + 4);
        chunk_store(g_Bh, t0, i0);
        chunk_store(g_Bh, t1, i1);
    }
}

// ============================================================================
// Pass 2: fused GEMM + LSTM cell.
//   CTA tile 128(M) x 128(packed N = 4 gates x 32 h-cols), BK=64.
//   8 warps 2(M) x 4(N); warp tile 64x32; mma m16n8k16 fp16->fp32.
// ============================================================================
static constexpr int TILE_BYTES  = 16384;                 // 128 x 128B
static constexpr int STAGE_BYTES = 2 * TILE_BYTES;        // A + B
static constexpr int STAGES      = 3;
static constexpr int KITERS      = 64;                    // 4096 / 64
static constexpr int SMEM_ALLOC  = STAGES * STAGE_BYTES + 1024;

__global__ __launch_bounds__(256, 2)
void lstm_gemm(const float* __restrict__ Bv, const float* __restrict__ Cin,
               float* __restrict__ Oh, float* __restrict__ Oc, float* __restrict__ Og)
{
    extern __shared__ unsigned char smraw[];
    __shared__ __align__(8) unsigned long long mbar_s[2 * STAGES];  // full[3], empty[3]
    __shared__ float s_bias[128];

    const int tid  = threadIdx.x;
    const int lane = tid & 31;
    const int w    = tid >> 5;
    const int wm   = w & 1;        // 0..1  (M)
    const int wn   = w >> 1;       // 0..3  (N)
    const int mtile = blockIdx.x & 31;   // 0..31
    const int ntile = blockIdx.x >> 5;   // 0..63 (h-col block of 32)

    const uint32_t smb = (smem_u32(smraw) + 1023u) & ~1023u;
    unsigned char* smal = smraw + (smb - smem_u32(smraw));
    const uint32_t mbb = smem_u32(&mbar_s[0]);     // full[s]  at mbb + s*8
    const uint32_t ebb = mbb + STAGES * 8;         // empty[s] at ebb + s*8

    if (tid == 0) {
        #pragma unroll
        for (int s = 0; s < STAGES; s++) {
            mbar_init(mbb + s * 8, 1);
            mbar_init(ebb + s * 8, 256);
        }
    }
    if (tid < 128)
        s_bias[tid] = Bv[(size_t)((tid >> 5) << 11) + (size_t)ntile * 32 + (tid & 31)];
    __syncthreads();

    const uint64_t gA = (uint64_t)(const void*)g_Ah + (uint64_t)(mtile * 64) * TILE_BYTES;
    const uint64_t gB = (uint64_t)(const void*)g_Bh + (uint64_t)(ntile * 64) * TILE_BYTES;

    auto produce = [&](int it, int s) {
        const uint32_t mb = mbb + s * 8;
        mbar_expect(mb, (uint32_t)STAGE_BYTES);
        bulk_g2s(smb + s * STAGE_BYTES,
                 (const void*)(gA + (uint64_t)it * TILE_BYTES), TILE_BYTES, mb);
        bulk_g2s(smb + s * STAGE_BYTES + TILE_BYTES,
                 (const void*)(gB + (uint64_t)it * TILE_BYTES), TILE_BYTES, mb);
    };
    if (tid == 0) { produce(0, 0); produce(1, 1); produce(2, 2); }

    // fragment address components (byte offsets inside a 16KB tile)
    uint32_t arow[4], brow4[2], cxA[4], cxB[4];
    #pragma unroll
    for (int mi = 0; mi < 4; mi++)
        arow[mi] = (uint32_t)((wm * 64 + mi * 16 + ((lane >> 3) & 1) * 8 + (lane & 7)) << 7);
    #pragma unroll
    for (int p = 0; p < 2; p++)   // ldmatrix.x4 covering n-frag pair (2p, 2p+1)
        brow4[p] = (uint32_t)(TILE_BYTES +
                   ((wn * 32 + p * 16 + ((lane >> 4) & 1) * 8 + (lane & 7)) << 7));
    #pragma unroll
    for (int ks = 0; ks < 4; ks++) {
        cxA[ks] = (uint32_t)((((2 * ks + (lane >> 4)) ^ (lane & 7)) << 4));
        cxB[ks] = (uint32_t)((((2 * ks + ((lane >> 3) & 1)) ^ (lane & 7)) << 4));
    }

    float acc[4][4][4];
    #pragma unroll
    for (int mi = 0; mi < 4; mi++)
        #pragma unroll
        for (int ni = 0; ni < 4; ni++)
            #pragma unroll
            for (int r = 0; r < 4; r++) acc[mi][ni][r] = 0.0f;

    uint32_t a[4][4];     // A fragments for current ks (all 4 mi groups)
    uint32_t bf[2][8];    // B double buffer (prefetch ks+1)

    // ---- prologue: wait stage 0, preload its B(ks=0) ----
    int st = 0;
    uint32_t trip = 0;
    uint32_t base = smb;
    mbar_wait(mbb + 0, 0);
    #pragma unroll
    for (int p = 0; p < 2; p++)
        asm volatile("ldmatrix.sync.aligned.m8n8.x4.shared.b16 {%0,%1,%2,%3}, [%4];"
                     : "=r"(bf[0][4*p+0]), "=r"(bf[0][4*p+1]),
                       "=r"(bf[0][4*p+2]), "=r"(bf[0][4*p+3])
                     : "r"(base + brow4[p] + cxB[0]));

    for (int it = 0; it < KITERS; it++) {
        #pragma unroll
        for (int ks = 0; ks < 4; ks++) {
            // hoisted A block: 4x ldmatrix.x4 (first HMMA waits only on a[0])
            #pragma unroll
            for (int mi = 0; mi < 4; mi++)
                asm volatile("ldmatrix.sync.aligned.m8n8.x4.shared.b16 {%0,%1,%2,%3}, [%4];"
                             : "=r"(a[mi][0]), "=r"(a[mi][1]), "=r"(a[mi][2]), "=r"(a[mi][3])
                             : "r"(base + arow[mi] + cxA[ks]));
            // prefetch next ks's B fragments
            if (ks < 3) {
                #pragma unroll
                for (int p = 0; p < 2; p++)
                    asm volatile("ldmatrix.sync.aligned.m8n8.x4.shared.b16 {%0,%1,%2,%3}, [%4];"
                                 : "=r"(bf[(ks+1)&1][4*p+0]), "=r"(bf[(ks+1)&1][4*p+1]),
                                   "=r"(bf[(ks+1)&1][4*p+2]), "=r"(bf[(ks+1)&1][4*p+3])
                                 : "r"(base + brow4[p] + cxB[ks+1]));
            }
            #pragma unroll
            for (int mi = 0; mi < 4; mi++) {
                #pragma unroll
                for (int ni = 0; ni < 4; ni++)
                    asm volatile(
                        "mma.sync.aligned.m16n8k16.row.col.f32.f16.f16.f32 "
                        "{%0,%1,%2,%3}, {%4,%5,%6,%7}, {%8,%9}, {%0,%1,%2,%3};"
                        : "+f"(acc[mi][ni][0]), "+f"(acc[mi][ni][1]),
                          "+f"(acc[mi][ni][2]), "+f"(acc[mi][ni][3])
                        : "r"(a[mi][0]), "r"(a[mi][1]), "r"(a[mi][2]), "r"(a[mi][3]),
                          "r"(bf[ks & 1][ni * 2]), "r"(bf[ks & 1][ni * 2 + 1]));
            }
        }

        // done reading stage st
        mbar_arrive(ebb + st * 8);

        if (tid == 0 && it + STAGES < KITERS) {
            mbar_wait(ebb + st * 8, trip & 1u);
            produce(it + STAGES, st);
        }

        // advance ring; seam preload of next stage's B(ks=0)
        const int nst = (st == STAGES - 1) ? 0 : st + 1;
        const uint32_t ntrip = (st == STAGES - 1) ? trip + 1 : trip;
        const uint32_t nbase = smb + nst * STAGE_BYTES;
        if (it + 1 < KITERS) {
            mbar_wait(mbb + nst * 8, ntrip & 1u);
            #pragma unroll
            for (int p = 0; p < 2; p++)
                asm volatile("ldmatrix.sync.aligned.m8n8.x4.shared.b16 {%0,%1,%2,%3}, [%4];"
                             : "=r"(bf[0][4*p+0]), "=r"(bf[0][4*p+1]),
                               "=r"(bf[0][4*p+2]), "=r"(bf[0][4*p+3])
                             : "r"(nbase + brow4[p] + cxB[0]));
        }
        base = nbase; st = nst; trip = ntrip;
    }

    // ------------- fused epilogue: acc -> SMEM -> gates -> outputs ---------
    __syncthreads();                               // pipeline fully drained
    float* sC = reinterpret_cast<float*>(smal);    // [128][132] fp32

    const size_t mbase = (size_t)mtile * 128;
    const size_t hb    = (size_t)ntile * 32;

    // prefetch Cin (overlaps with acc->SMEM transpose + barrier)
    float cin[16];
    #pragma unroll
    for (int kk = 0; kk < 16; kk++) {
        const int idx = kk * 256 + tid;
        const int m = idx >> 5, cc = idx & 31;
        cin[kk] = Cin[(mbase + m) * 2048 + hb + cc];
    }

    #pragma unroll
    for (int mi = 0; mi < 4; mi++) {
        const int r0 = wm * 64 + mi * 16 + (lane >> 2);
        #pragma unroll
        for (int ni = 0; ni < 4; ni++) {
            const int c0 = wn * 32 + ni * 8 + (lane & 3) * 2;
            *reinterpret_cast<float2*>(&sC[r0 * 132 + c0]) =
                make_float2(acc[mi][ni][0], acc[mi][ni][1]);
            *reinterpret_cast<float2*>(&sC[(r0 + 8) * 132 + c0]) =
                make_float2(acc[mi][ni][2], acc[mi][ni][3]);
        }
    }
    __syncthreads();

    #pragma unroll
    for (int kk = 0; kk < 16; kk++) {
        const int idx = kk * 256 + tid;
        const int m = idx >> 5, cc = idx & 31;
        const float gf = sC[m * 132 +       cc] + s_bias[cc];
        const float gi = sC[m * 132 +  32 + cc] + s_bias[32 + cc];
        const float gs = sC[m * 132 +  64 + cc] + s_bias[64 + cc];
        const float gg = sC[m * 132 +  96 + cc] + s_bias[96 + cc];

        const float f  = sigf(gf);
        const float ii = sigf(gi);
        const float ss = tanhp(gs);
        const float oo = sigf(gg);
        const float cn = f * cin[kk] + ii * ss;
        const float hn = oo * tanhp(cn);

        const size_t off = (mbase + m) * 2048 + hb + cc;
        Oh[off] = hn;
        Oc[off] = cn;
        Og[off] = oo;
    }
}

// ============================================================================
// launch
// ============================================================================
extern "C" void kernel_launch(void* const* d_in, const int* in_sizes, int n_in,
                              void* d_out, int out_size)
{
    const float* x    = (const float*)d_in[0];
    const float* h    = (const float*)d_in[1];
    const float* c    = (const float*)d_in[2];
    /* d_in[3] = o, unused by the reference computation */
    const float* w_ih = (const float*)d_in[4];
    const float* w_hh = (const float*)d_in[5];
    const float* b    = (const float*)d_in[6];
    float* out = (float*)d_out;

    cudaFuncSetAttribute(lstm_gemm,
                         cudaFuncAttributeMaxDynamicSharedMemorySize, SMEM_ALLOC);

    cvt_pack<<<12288, 256>>>(x, h, w_ih, w_hh);

    float* out_h  = out;
    float* out_c  = out + (size_t)4096 * 2048;
    float* out_go = out + (size_t)2 * 4096 * 2048;
    lstm_gemm<<<2048, 256, SMEM_ALLOC>>>(b, c, out_h, out_c, out_go);
}

// round 8
// speedup vs baseline: 1.0258x; 1.0258x over previous
#include <cuda_runtime.h>
#include <cuda_fp16.h>
#include <cstdint>

// ============================================================================
// LSTMCell for GB300 — sm_103 (non-'a') path: fp16 mma.sync + cp.async.bulk.
//
//   Pass 1 (single kernel): fp32 -> fp16 (RN), pre-tiled + SW128-swizzled,
//           4 chunks/thread with front-batched loads (MLP=8).
//   Pass 2: GEMM 128x128x(BK=64), 3-stage bulk-copy mbarrier ring
//           (R5 ordering — known-best), per-warp empty arrives (count=8),
//           fused fast-math LSTM epilogue with Cin prefetch.
// ============================================================================

#define DINLINE __device__ __forceinline__

__device__ __align__(1024) __half g_Ah[4096UL * 4096];   // 32 MB
__device__ __align__(1024) __half g_Bh[8192UL * 4096];   // 64 MB

// ------------------------------- helpers -----------------------------------
DINLINE uint32_t smem_u32(const void* p) {
    uint32_t a;
    asm("{ .reg .u64 t; cvta.to.shared.u64 t, %1; cvt.u32.u64 %0, t; }"
        : "=r"(a) : "l"(p));
    return a;
}

DINLINE void mbar_init(uint32_t a, uint32_t cnt) {
    asm volatile("mbarrier.init.shared.b64 [%0], %1;" :: "r"(a), "r"(cnt) : "memory");
}
DINLINE void mbar_expect(uint32_t a, uint32_t tx) {
    asm volatile("mbarrier.arrive.expect_tx.shared.b64 _, [%0], %1;"
                 :: "r"(a), "r"(tx) : "memory");
}
DINLINE void mbar_arrive(uint32_t a) {
    asm volatile("mbarrier.arrive.shared.b64 _, [%0];" :: "r"(a) : "memory");
}
DINLINE void mbar_wait(uint32_t mbar, uint32_t parity) {
    uint32_t done;
    asm volatile(
        "{\n .reg .pred p;\n"
        " mbarrier.try_wait.parity.acquire.cta.shared::cta.b64 p, [%1], %2;\n"
        " selp.b32 %0, 1, 0, p;\n}"
        : "=r"(done) : "r"(mbar), "r"(parity) : "memory");
    if (!done) {
        asm volatile(
            "{\n .reg .pred P1;\n"
            "WL%=:\n"
            " mbarrier.try_wait.parity.acquire.cta.shared::cta.b64 P1, [%0], %1, 0x989680;\n"
            " @P1 bra.uni WD%=;\n"
            " bra.uni WL%=;\n"
            "WD%=:\n}"
            :: "r"(mbar), "r"(parity) : "memory");
    }
}

DINLINE void bulk_g2s(uint32_t dst, const void* src, uint32_t bytes, uint32_t mbar) {
    asm volatile(
        "cp.async.bulk.shared::cluster.global.mbarrier::complete_tx::bytes [%0], [%1], %2, [%3];"
        :: "r"(dst), "l"(src), "r"(bytes), "r"(mbar) : "memory");
}

// fast-math gates (ex2/rcp approx; errors ~1e-7, negligible vs fp16 inputs)
DINLINE float ex2a(float x) { float y; asm("ex2.approx.f32 %0, %1;" : "=f"(y) : "f"(x)); return y; }
DINLINE float rcpa(float x) { float y; asm("rcp.approx.f32 %0, %1;" : "=f"(y) : "f"(x)); return y; }
DINLINE float sigf(float x)  { return rcpa(1.0f + ex2a(-1.442695041f * x)); }
DINLINE float tanhp(float x) { return 2.0f * sigf(2.0f * x) - 1.0f; }

// ============================================================================
// Pass 1: convert + tile + swizzle.  Chunk = 16B of fp16 (8 halves).
//   chunk id bits: [c:3][m:7][kc:6][tile:rest]
//   4 chunks per thread, all 8 LDG.128 issued before converts (MLP=8).
// ============================================================================
DINLINE const float* chunk_src(const float* a, const float* b,
                               uint32_t t, int which)
{
    const uint32_t c = t & 7u;
    const uint32_t m = (t >> 3) & 127u;
    const uint32_t k = ((t >> 10) & 63u) * 64u + c * 8u;
    const uint32_t tile = t >> 16;
    uint32_t src_row;
    if (which) src_row = ((m >> 5) << 11) + tile * 32u + (m & 31u);
    else       src_row = tile * 128u + m;
    const size_t srow = (size_t)src_row * 2048;
    return (k < 2048u) ? (a + srow + k) : (b + srow + (k - 2048u));
}

DINLINE void chunk_store(__half* dstbuf, uint32_t t,
                         const float4& v0, const float4& v1)
{
    __half2 h0 = __floats2half2_rn(v0.x, v0.y);
    __half2 h1 = __floats2half2_rn(v0.z, v0.w);
    __half2 h2 = __floats2half2_rn(v1.x, v1.y);
    __half2 h3 = __floats2half2_rn(v1.z, v1.w);
    uint4 out;
    out.x = *reinterpret_cast<uint32_t*>(&h0);
    out.y = *reinterpret_cast<uint32_t*>(&h1);
    out.z = *reinterpret_cast<uint32_t*>(&h2);
    out.w = *reinterpret_cast<uint32_t*>(&h3);
    const uint32_t c = t & 7u, m = (t >> 3) & 127u;
    *reinterpret_cast<uint4*>((unsigned char*)dstbuf +
        ((size_t)(t >> 3) << 7) + ((c ^ (m & 7u)) << 4)) = out;
}

__global__ __launch_bounds__(256)
void cvt_pack(const float* __restrict__ x,  const float* __restrict__ h,
              const float* __restrict__ wi, const float* __restrict__ wh)
{
    const uint32_t g = blockIdx.x * 256u + threadIdx.x;
    float4 v[8];
    uint32_t t[4];

    if (g < (1u << 19)) {
        // A: 2^21 chunks, 4 per thread
        #pragma unroll
        for (int j = 0; j < 4; j++) t[j] = g + (uint32_t)j * (1u << 19);
        #pragma unroll
        for (int j = 0; j < 4; j++) {
            const float* s = chunk_src(x, h, t[j], 0);
            v[2*j]   = *reinterpret_cast<const float4*>(s);
            v[2*j+1] = *reinterpret_cast<const float4*>(s + 4);
        }
        #pragma unroll
        for (int j = 0; j < 4; j++) chunk_store(g_Ah, t[j], v[2*j], v[2*j+1]);
    } else {
        // B: 2^22 chunks, 4 per thread
        const uint32_t q = g - (1u << 19);
        #pragma unroll
        for (int j = 0; j < 4; j++) t[j] = q + (uint32_t)j * (1u << 20);
        #pragma unroll
        for (int j = 0; j < 4; j++) {
            const float* s = chunk_src(wi, wh, t[j], 1);
            v[2*j]   = *reinterpret_cast<const float4*>(s);
            v[2*j+1] = *reinterpret_cast<const float4*>(s + 4);
        }
        #pragma unroll
        for (int j = 0; j < 4; j++) chunk_store(g_Bh, t[j], v[2*j], v[2*j+1]);
    }
}

// ============================================================================
// Pass 2: fused GEMM + LSTM cell.
//   CTA tile 128(M) x 128(packed N = 4 gates x 32 h-cols), BK=64.
//   8 warps 2(M) x 4(N); warp tile 64x32; mma m16n8k16 fp16->fp32.
//   Pipeline: full[s] (tx mbarrier) + empty[s] (count-8, per-warp arrive).
// ============================================================================
static constexpr int TILE_BYTES  = 16384;                 // 128 x 128B
static constexpr int STAGE_BYTES = 2 * TILE_BYTES;        // A + B
static constexpr int STAGES      = 3;
static constexpr int KITERS      = 64;                    // 4096 / 64
static constexpr int SMEM_ALLOC  = STAGES * STAGE_BYTES + 1024;

__global__ __launch_bounds__(256, 2)
void lstm_gemm(const float* __restrict__ Bv, const float* __restrict__ Cin,
               float* __restrict__ Oh, float* __restrict__ Oc, float* __restrict__ Og)
{
    extern __shared__ unsigned char smraw[];
    __shared__ __align__(8) unsigned long long mbar_s[2 * STAGES];  // full[3], empty[3]
    __shared__ float s_bias[128];

    const int tid  = threadIdx.x;
    const int lane = tid & 31;
    const int w    = tid >> 5;
    const int wm   = w & 1;        // 0..1  (M)
    const int wn   = w >> 1;       // 0..3  (N)
    const int mtile = blockIdx.x & 31;   // 0..31
    const int ntile = blockIdx.x >> 5;   // 0..63 (h-col block of 32)

    const uint32_t smb = (smem_u32(smraw) + 1023u) & ~1023u;
    unsigned char* smal = smraw + (smb - smem_u32(smraw));
    const uint32_t mbb = smem_u32(&mbar_s[0]);     // full[s]  at mbb + s*8
    const uint32_t ebb = mbb + STAGES * 8;         // empty[s] at ebb + s*8

    if (tid == 0) {
        #pragma unroll
        for (int s = 0; s < STAGES; s++) {
            mbar_init(mbb + s * 8, 1);
            mbar_init(ebb + s * 8, 8);             // one arrive per warp
        }
    }
    if (tid < 128)
        s_bias[tid] = Bv[(size_t)((tid >> 5) << 11) + (size_t)ntile * 32 + (tid & 31)];
    __syncthreads();

    const uint64_t gA = (uint64_t)(const void*)g_Ah + (uint64_t)(mtile * 64) * TILE_BYTES;
    const uint64_t gB = (uint64_t)(const void*)g_Bh + (uint64_t)(ntile * 64) * TILE_BYTES;

    auto produce = [&](int it, int s) {
        const uint32_t mb = mbb + s * 8;
        mbar_expect(mb, (uint32_t)STAGE_BYTES);
        bulk_g2s(smb + s * STAGE_BYTES,
                 (const void*)(gA + (uint64_t)it * TILE_BYTES), TILE_BYTES, mb);
        bulk_g2s(smb + s * STAGE_BYTES + TILE_BYTES,
                 (const void*)(gB + (uint64_t)it * TILE_BYTES), TILE_BYTES, mb);
    };
    if (tid == 0) { produce(0, 0); produce(1, 1); produce(2, 2); }

    // fragment address components (byte offsets inside a 16KB tile)
    uint32_t arow[4], brow4[2], cxA[4], cxB[4];
    #pragma unroll
    for (int mi = 0; mi < 4; mi++)
        arow[mi] = (uint32_t)((wm * 64 + mi * 16 + ((lane >> 3) & 1) * 8 + (lane & 7)) << 7);
    #pragma unroll
    for (int p = 0; p < 2; p++)   // ldmatrix.x4 covering n-frag pair (2p, 2p+1)
        brow4[p] = (uint32_t)(TILE_BYTES +
                   ((wn * 32 + p * 16 + ((lane >> 4) & 1) * 8 + (lane & 7)) << 7));
    #pragma unroll
    for (int ks = 0; ks < 4; ks++) {
        cxA[ks] = (uint32_t)((((2 * ks + (lane >> 4)) ^ (lane & 7)) << 4));
        cxB[ks] = (uint32_t)((((2 * ks + ((lane >> 3) & 1)) ^ (lane & 7)) << 4));
    }

    float acc[4][4][4];
    #pragma unroll
    for (int mi = 0; mi < 4; mi++)
        #pragma unroll
        for (int ni = 0; ni < 4; ni++)
            #pragma unroll
            for (int r = 0; r < 4; r++) acc[mi][ni][r] = 0.0f;

    // ring state: at iteration it, parity for full-wait and empty-wait is
    // (it / STAGES) & 1, tracked incrementally via `trip`.
    int st = 0;
    uint32_t trip = 0;

    for (int it = 0; it < KITERS; it++) {
        const uint32_t par = trip & 1u;
        mbar_wait(mbb + st * 8, par);
        const uint32_t base = smb + st * STAGE_BYTES;

        #pragma unroll
        for (int ks = 0; ks < 4; ks++) {
            uint32_t b0[4], b1[4];
            #pragma unroll
            for (int p = 0; p < 2; p++)
                asm volatile("ldmatrix.sync.aligned.m8n8.x4.shared.b16 {%0,%1,%2,%3}, [%4];"
                             : "=r"(b0[2*p]), "=r"(b1[2*p]), "=r"(b0[2*p+1]), "=r"(b1[2*p+1])
                             : "r"(base + brow4[p] + cxB[ks]));
            #pragma unroll
            for (int mi = 0; mi < 4; mi++) {
                uint32_t a0, a1, a2, a3;
                asm volatile("ldmatrix.sync.aligned.m8n8.x4.shared.b16 {%0,%1,%2,%3}, [%4];"
                             : "=r"(a0), "=r"(a1), "=r"(a2), "=r"(a3)
                             : "r"(base + arow[mi] + cxA[ks]));
                #pragma unroll
                for (int ni = 0; ni < 4; ni++)
                    asm volatile(
                        "mma.sync.aligned.m16n8k16.row.col.f32.f16.f16.f32 "
                        "{%0,%1,%2,%3}, {%4,%5,%6,%7}, {%8,%9}, {%0,%1,%2,%3};"
                        : "+f"(acc[mi][ni][0]), "+f"(acc[mi][ni][1]),
                          "+f"(acc[mi][ni][2]), "+f"(acc[mi][ni][3])
                        : "r"(a0), "r"(a1), "r"(a2), "r"(a3),
                          "r"(b0[ni]), "r"(b1[ni]));
            }
        }

        // warp done reading stage st (warp-collective ops => whole warp done)
        if (lane == 0) mbar_arrive(ebb + st * 8);

        // producer: refill st for iteration it+STAGES once all warps arrived
        if (tid == 0 && it + STAGES < KITERS) {
            mbar_wait(ebb + st * 8, trip & 1u);
            produce(it + STAGES, st);
        }

        if (++st == STAGES) { st = 0; trip++; }
    }

    // ------------- fused epilogue: acc -> SMEM -> gates -> outputs ---------
    __syncthreads();                               // pipeline fully drained
    float* sC = reinterpret_cast<float*>(smal);    // [128][132] fp32

    const size_t mbase = (size_t)mtile * 128;
    const size_t hb    = (size_t)ntile * 32;

    // prefetch Cin (overlaps with acc->SMEM transpose + barrier)
    float cin[16];
    #pragma unroll
    for (int kk = 0; kk < 16; kk++) {
        const int idx = kk * 256 + tid;
        const int m = idx >> 5, cc = idx & 31;
        cin[kk] = Cin[(mbase + m) * 2048 + hb + cc];
    }

    #pragma unroll
    for (int mi = 0; mi < 4; mi++) {
        const int r0 = wm * 64 + mi * 16 + (lane >> 2);
        #pragma unroll
        for (int ni = 0; ni < 4; ni++) {
            const int c0 = wn * 32 + ni * 8 + (lane & 3) * 2;
            *reinterpret_cast<float2*>(&sC[r0 * 132 + c0]) =
                make_float2(acc[mi][ni][0], acc[mi][ni][1]);
            *reinterpret_cast<float2*>(&sC[(r0 + 8) * 132 + c0]) =
                make_float2(acc[mi][ni][2], acc[mi][ni][3]);
        }
    }
    __syncthreads();

    #pragma unroll
    for (int kk = 0; kk < 16; kk++) {
        const int idx = kk * 256 + tid;
        const int m = idx >> 5, cc = idx & 31;
        const float gf = sC[m * 132 +       cc] + s_bias[cc];
        const float gi = sC[m * 132 +  32 + cc] + s_bias[32 + cc];
        const float gs = sC[m * 132 +  64 + cc] + s_bias[64 + cc];
        const float gg = sC[m * 132 +  96 + cc] + s_bias[96 + cc];

        const float f  = sigf(gf);
        const float ii = sigf(gi);
        const float ss = tanhp(gs);
        const float oo = sigf(gg);
        const float cn = f * cin[kk] + ii * ss;
        const float hn = oo * tanhp(cn);

        const size_t off = (mbase + m) * 2048 + hb + cc;
        Oh[off] = hn;
        Oc[off] = cn;
        Og[off] = oo;
    }
}

// ============================================================================
// launch
// ============================================================================
extern "C" void kernel_launch(void* const* d_in, const int* in_sizes, int n_in,
                              void* d_out, int out_size)
{
    const float* x    = (const float*)d_in[0];
    const float* h    = (const float*)d_in[1];
    const float* c    = (const float*)d_in[2];
    /* d_in[3] = o, unused by the reference computation */
    const float* w_ih = (const float*)d_in[4];
    const float* w_hh = (const float*)d_in[5];
    const float* b    = (const float*)d_in[6];
    float* out = (float*)d_out;

    cudaFuncSetAttribute(lstm_gemm,
                         cudaFuncAttributeMaxDynamicSharedMemorySize, SMEM_ALLOC);

    cvt_pack<<<6144, 256>>>(x, h, w_ih, w_hh);

    float* out_h  = out;
    float* out_c  = out + (size_t)4096 * 2048;
    float* out_go = out + (size_t)2 * 4096 * 2048;
    lstm_gemm<<<2048, 256, SMEM_ALLOC>>>(b, c, out_h, out_c, out_go);
}